// round 13
// baseline (speedup 1.0000x reference)
#include <cuda_runtime.h>
#include <cstdint>

// NodeDropout: out[e] = values[e] * keep[src[e]] * keep[dst[e]],  keep[i] = !nodes_flag[i]
//
// Layout (pinned by R4-R6 evidence on this bench):
//   d_in[0] : edge_index  (2, E) row-major, int32
//   d_in[1] : values      float32, E
//   d_in[2] : nodes_flag  N x 4-byte words (nonzero = dropped)
// Output: float32, E.
//
// K1: pack flag words -> 122 KB keep-bitmask (__device__ global).
// K2: 1 CTA/SM (dyn smem = bitmask), bitmask staged in shared memory;
//     1024 threads, dual-quad grid-stride (R7 champion structure) with
//     streaming (.cs) loads/stores on all single-use data.

#define MAX_BIT_WORDS 32768   // up to 1,048,576 nodes

__device__ uint32_t g_keep_bits[MAX_BIT_WORDS];

// ---------------------------------------------------------------------------
// K1: pack 4-byte flags -> keep bitmask (bit = 1 means node is KEPT)
// ---------------------------------------------------------------------------
__global__ void pack_flags_kernel(const uint32_t* __restrict__ flags,
                                  int n_nodes, int n_words) {
    int t = blockIdx.x * blockDim.x + threadIdx.x;
    if (t >= n_words) return;

    const int base = t * 32;
    uint32_t  w    = 0;

    if (base + 32 <= n_nodes) {
        const uint4* p = reinterpret_cast<const uint4*>(flags + base);  // 128 B
#pragma unroll
        for (int c = 0; c < 8; c++) {
            uint4 q = p[c];
            w |= (q.x ? 0u : 1u) << (c * 4 + 0);
            w |= (q.y ? 0u : 1u) << (c * 4 + 1);
            w |= (q.z ? 0u : 1u) << (c * 4 + 2);
            w |= (q.w ? 0u : 1u) << (c * 4 + 3);
        }
    } else {
        int lim = n_nodes - base;
        for (int j = 0; j < 32; j++) {
            uint32_t fv = (j < lim) ? flags[base + j] : 1u;  // OOB = dropped
            w |= (fv ? 0u : 1u) << j;
        }
    }
    g_keep_bits[t] = w;
}

// ---------------------------------------------------------------------------
// K2: masked edge scaling with smem-resident bitmask
// ---------------------------------------------------------------------------
__device__ __forceinline__ uint32_t keep2(const uint32_t* __restrict__ s_bits,
                                          uint32_t s, uint32_t d) {
    return (s_bits[s >> 5] >> (s & 31)) & (s_bits[d >> 5] >> (d & 31)) & 1u;
}

__device__ __forceinline__ void do_quad(const int* __restrict__ src,
                                        const int* __restrict__ dst,
                                        const float* __restrict__ vals,
                                        float* __restrict__ out,
                                        const uint32_t* __restrict__ s_bits,
                                        int e) {
    int4   s4 = __ldcs(reinterpret_cast<const int4*>(src + e));
    int4   d4 = __ldcs(reinterpret_cast<const int4*>(dst + e));
    float4 v  = __ldcs(reinterpret_cast<const float4*>(vals + e));

    uint32_t ka = keep2(s_bits, (uint32_t)s4.x, (uint32_t)d4.x);
    uint32_t kb = keep2(s_bits, (uint32_t)s4.y, (uint32_t)d4.y);
    uint32_t kc = keep2(s_bits, (uint32_t)s4.z, (uint32_t)d4.z);
    uint32_t kd = keep2(s_bits, (uint32_t)s4.w, (uint32_t)d4.w);

    float4 o;
    o.x = ka ? v.x : 0.0f;
    o.y = kb ? v.y : 0.0f;
    o.z = kc ? v.z : 0.0f;
    o.w = kd ? v.w : 0.0f;
    __stcs(reinterpret_cast<float4*>(out + e), o);
}

__global__ __launch_bounds__(1024, 1)
void node_dropout_kernel(const int* __restrict__ ei,
                         const float* __restrict__ vals,
                         float* __restrict__ out,
                         int E, int n_words) {
    extern __shared__ uint32_t s_bits[];

    // Stage bitmask (coalesced; L2-hot right after pack kernel).
    for (int i = threadIdx.x; i < n_words; i += blockDim.x)
        s_bits[i] = g_keep_bits[i];
    __syncthreads();

    const int* __restrict__ src = ei;
    const int* __restrict__ dst = ei + E;

    const int quads  = E >> 2;
    const int stride = gridDim.x * blockDim.x;
    int       q      = blockIdx.x * blockDim.x + threadIdx.x;

    // Dual-quad main loop: 6 independent 128-bit loads in flight per thread.
    for (; q + stride < quads; q += 2 * stride) {
        do_quad(src, dst, vals, out, s_bits, q << 2);
        do_quad(src, dst, vals, out, s_bits, (q + stride) << 2);
    }
    if (q < quads)
        do_quad(src, dst, vals, out, s_bits, q << 2);

    // Tail edges (E % 4).
    int gtid = blockIdx.x * blockDim.x + threadIdx.x;
    int e = (quads << 2) + gtid;
    if (e < E) {
        uint32_t k = keep2(s_bits, (uint32_t)src[e], (uint32_t)dst[e]);
        out[e] = k ? vals[e] : 0.0f;
    }
}

// ---------------------------------------------------------------------------
// Launch
// ---------------------------------------------------------------------------
extern "C" void kernel_launch(void* const* d_in, const int* in_sizes, int n_in,
                              void* d_out, int out_size) {
    const int*      ei    = (const int*)d_in[0];
    const float*    vals  = (const float*)d_in[1];
    const uint32_t* flags = (const uint32_t*)d_in[2];
    float*          out   = (float*)d_out;

    const int E       = in_sizes[0] / 2;
    const int n_nodes = in_sizes[2];
    const int n_words = (n_nodes + 31) / 32;

    // K1: pack flags into keep-bitmask
    {
        int threads = 256;
        int blocks  = (n_words + threads - 1) / threads;
        pack_flags_kernel<<<blocks, threads>>>(flags, n_nodes, n_words);
    }

    // K2: masked scaling with smem bitmask
    {
        int sm_count = 148;
        cudaDeviceGetAttribute(&sm_count, cudaDevAttrMultiProcessorCount, 0);

        size_t smem_bytes = (size_t)n_words * sizeof(uint32_t);
        cudaFuncSetAttribute(node_dropout_kernel,
                             cudaFuncAttributeMaxDynamicSharedMemorySize,
                             (int)smem_bytes);

        node_dropout_kernel<<<sm_count, 1024, smem_bytes>>>(ei, vals, out, E, n_words);
    }
}